// round 5
// baseline (speedup 1.0000x reference)
#include <cuda_runtime.h>
#include <cuda_bf16.h>
#include <cstdint>

// Problem constants
#define NB 4
#define NS 1024
#define ND 1024
#define NF 4096
#define NV 32000
#define NL 4

// ---------------------------------------------------------------------------
// Scratch (device globals: no allocation allowed)
// ---------------------------------------------------------------------------
__device__ float g_x  [(size_t)NB * NS * ND];    // activation stream fp32
__device__ float g_tmp[(size_t)NB * NS * ND];    // attn_out / ffn_out fp32

__device__ __nv_bfloat16 g_xh [(size_t)NB * NS * ND];
__device__ __nv_bfloat16 g_xl [(size_t)NB * NS * ND];
__device__ __nv_bfloat16 g_xth[(size_t)NB * ND * NS];   // x^T per batch
__device__ __nv_bfloat16 g_xtl[(size_t)NB * ND * NS];
__device__ __nv_bfloat16 g_ah [(size_t)NB * NS * NS];   // attn probs split
__device__ __nv_bfloat16 g_al [(size_t)NB * NS * NS];
__device__ __nv_bfloat16 g_hh [(size_t)NB * NS * NF];   // ffn hidden split
__device__ __nv_bfloat16 g_hl [(size_t)NB * NS * NF];
__device__ __nv_bfloat16 g_w1h[(size_t)NL * NF * ND];   // w1^T split
__device__ __nv_bfloat16 g_w1l[(size_t)NL * NF * ND];
__device__ __nv_bfloat16 g_w2h[(size_t)NL * ND * NF];   // w2^T split
__device__ __nv_bfloat16 g_w2l[(size_t)NL * ND * NF];
__device__ __nv_bfloat16 g_wvh[(size_t)NV * ND];        // headW^T split
__device__ __nv_bfloat16 g_wvl[(size_t)NV * ND];

// ---------------------------------------------------------------------------
// Helpers
// ---------------------------------------------------------------------------
__device__ __forceinline__ uint32_t smem_u32(const void* p) {
    return (uint32_t)__cvta_generic_to_shared(p);
}
__device__ __forceinline__ void split_bf16(float v, __nv_bfloat16& h, __nv_bfloat16& l) {
    h = __float2bfloat16(v);
    l = __float2bfloat16(v - __bfloat162float(h));
}

#define CP16(smem, gptr) \
    asm volatile("cp.async.cg.shared.global [%0], [%1], 16;" :: "r"(smem), "l"(gptr))
#define CP_COMMIT() asm volatile("cp.async.commit_group;" ::: "memory")
#define CP_WAIT0() asm volatile("cp.async.wait_group 0;" ::: "memory")
#define CP_WAIT1() asm volatile("cp.async.wait_group 1;" ::: "memory")
#define CP_WAIT2() asm volatile("cp.async.wait_group 2;" ::: "memory")

#define LDSM_X4(r0, r1, r2, r3, addr) \
    asm volatile("ldmatrix.sync.aligned.m8n8.x4.shared.b16 {%0,%1,%2,%3}, [%4];" \
                 : "=r"(r0), "=r"(r1), "=r"(r2), "=r"(r3) : "r"(addr))

#define MMA16816(c, a, b) \
    asm("mma.sync.aligned.m16n8k16.row.col.f32.bf16.bf16.f32 " \
        "{%0,%1,%2,%3}, {%4,%5,%6,%7}, {%8,%9}, {%0,%1,%2,%3};" \
        : "+f"((c)[0]), "+f"((c)[1]), "+f"((c)[2]), "+f"((c)[3]) \
        : "r"((a)[0]), "r"((a)[1]), "r"((a)[2]), "r"((a)[3]), "r"((b)[0]), "r"((b)[1]))

// ---------------------------------------------------------------------------
// HMMA GEMM: C[M,N] = alpha * (Ah@Bh^T + Ah@Bl^T + Al@Bh^T) (+bias)(+relu).
// A as Ah/Al [M,K] row-major; B as Bh/Bl [N,K] row-major (K-major).
// Tile: BM=256, BN=128, BK=32. 256 threads, warp grid 4x2 (warp tile 64x64).
// 3-stage cp.async pipeline. Smem rows padded to 80B (conflict-free ldmatrix).
// SPLIT: write bf16 hi/lo. CTRI: skip blocks above diagonal. CKLIM: K->brow+256.
// ---------------------------------------------------------------------------
static constexpr int A_TILE_B = 256 * 80;         // 20480 per A operand (hi or lo)
static constexpr int B_TILE_B = 128 * 80;         // 10240 per B operand
static constexpr int AH_O = 0;
static constexpr int AL_O = A_TILE_B;             // 20480
static constexpr int BH_O = 2 * A_TILE_B;         // 40960
static constexpr int BL_O = 2 * A_TILE_B + B_TILE_B;  // 51200
static constexpr int STAGE_B = 2 * A_TILE_B + 2 * B_TILE_B;  // 61440
static constexpr int SMEM_DYN = 3 * STAGE_B;      // 184320

template<bool RELU, bool SPLIT, bool CTRI, bool CKLIM>
__global__ __launch_bounds__(256)
void hmma_gemm(const __nv_bfloat16* __restrict__ Ah, const __nv_bfloat16* __restrict__ Al,
               const __nv_bfloat16* __restrict__ Bh, const __nv_bfloat16* __restrict__ Bl,
               float* __restrict__ C, __nv_bfloat16* __restrict__ Ch,
               __nv_bfloat16* __restrict__ Cl,
               int M, int N, int K,
               long sA, long sB, long sC,
               float alpha, const float* __restrict__ bias)
{
    const int brow = blockIdx.y * 256;
    const int bcol = blockIdx.x * 128;
    if (CTRI && bcol >= brow + 256) return;

    Ah += (long)blockIdx.z * sA;  Al += (long)blockIdx.z * sA;
    Bh += (long)blockIdx.z * sB;  Bl += (long)blockIdx.z * sB;
    if (C)  C  += (long)blockIdx.z * sC;
    if (Ch) { Ch += (long)blockIdx.z * sC; Cl += (long)blockIdx.z * sC; }

    const int tid  = threadIdx.x;
    const int wid  = tid >> 5;
    const int lane = tid & 31;
    const int wm   = wid & 3;          // warp row (0..3) -> 64 rows each
    const int wn   = wid >> 2;         // warp col (0..1) -> 64 cols each

    const int K_eff = CKLIM ? (brow + 256 < K ? brow + 256 : K) : K;
    const int nk = K_eff >> 5;

    extern __shared__ __align__(16) char dsm[];
    const uint32_t sbase = smem_u32(dsm);
    __shared__ float s_bias[128];
    if (tid < 128) s_bias[tid] = bias ? bias[bcol + tid] : 0.0f;

    float acc[4][8][4] = {};   // [mi][ni][frag]

    // ldmatrix per-lane address components (element offsets within a tile)
    const int a_row = (lane & 15);                      // + wm*64 + mi*16
    const int a_ko  = (lane >> 4) << 3;                 // + ks*16
    const int b_row = ((lane >> 4) << 3) + (lane & 7);  // + wn*64 + p*16
    const int b_ko  = ((lane >> 3) & 1) << 3;           // + ks*16

    // loader: 3072 16B chunks per stage, 12 per thread
    auto load_stage = [&](int stage, int kk) {
        const uint32_t sb = sbase + stage * STAGE_B;
        #pragma unroll
        for (int i = 0; i < 12; i++) {
            int chunk = tid + i * 256;
            int r, c;
            const __nv_bfloat16* g;
            uint32_t so;
            if (chunk < 2048) {                 // A: 2 ops x 256 rows x 4 chunks
                int op = chunk >> 10;           // 0:Ah 1:Al
                int w = chunk & 1023;
                r = w >> 2; c = w & 3;
                g = (op ? Al : Ah) + (long)(brow + r) * K + kk + c * 8;
                so = sb + (op ? AL_O : AH_O) + r * 80 + c * 16;
            } else {                            // B: 2 ops x 128 rows x 4 chunks
                int j = chunk - 2048;
                int op = j >> 9;                // 0:Bh 1:Bl
                int w = j & 511;
                r = w >> 2; c = w & 3;
                g = (op ? Bl : Bh) + (long)(bcol + r) * K + kk + c * 8;
                so = sb + (op ? BL_O : BH_O) + r * 80 + c * 16;
            }
            CP16(so, g);
        }
    };

    // prologue: up to 3 stages in flight
    load_stage(0, 0); CP_COMMIT();
    if (nk > 1) { load_stage(1, 32); CP_COMMIT(); }
    if (nk > 2) { load_stage(2, 64); CP_COMMIT(); }

    for (int kc = 0; kc < nk; kc++) {
        const int rem = nk - 1 - kc;
        if (rem >= 2)      CP_WAIT2();
        else if (rem == 1) CP_WAIT1();
        else               CP_WAIT0();
        __syncthreads();

        const uint32_t st = sbase + (kc % 3) * STAGE_B;
        const uint32_t ahb = st + AH_O;
        const uint32_t alb = st + AL_O;
        const uint32_t bhb = st + BH_O;
        const uint32_t blb = st + BL_O;

        #pragma unroll
        for (int ks = 0; ks < 2; ks++) {
            const int ak = (ks * 16 + a_ko) * 2;
            const int bk = (ks * 16 + b_ko) * 2;

            uint32_t af[4][4], bf[8][2];
            #pragma unroll
            for (int mi = 0; mi < 4; mi++) {
                uint32_t ad = ahb + (wm * 64 + mi * 16 + a_row) * 80 + ak;
                LDSM_X4(af[mi][0], af[mi][1], af[mi][2], af[mi][3], ad);
            }
            #pragma unroll
            for (int p = 0; p < 4; p++) {
                uint32_t bd = bhb + (wn * 64 + p * 16 + b_row) * 80 + bk;
                LDSM_X4(bf[2*p][0], bf[2*p][1], bf[2*p+1][0], bf[2*p+1][1], bd);
            }
            #pragma unroll
            for (int mi = 0; mi < 4; mi++)
                #pragma unroll
                for (int ni = 0; ni < 8; ni++)
                    MMA16816(acc[mi][ni], af[mi], bf[ni]);   // Ah*Bh

            uint32_t lf[8][2];
            #pragma unroll
            for (int p = 0; p < 4; p++) {
                uint32_t bd = blb + (wn * 64 + p * 16 + b_row) * 80 + bk;
                LDSM_X4(lf[2*p][0], lf[2*p][1], lf[2*p+1][0], lf[2*p+1][1], bd);
            }
            #pragma unroll
            for (int mi = 0; mi < 4; mi++)
                #pragma unroll
                for (int ni = 0; ni < 8; ni++)
                    MMA16816(acc[mi][ni], af[mi], lf[ni]);   // Ah*Bl

            #pragma unroll
            for (int mi = 0; mi < 4; mi++) {
                uint32_t ad = alb + (wm * 64 + mi * 16 + a_row) * 80 + ak;
                LDSM_X4(af[mi][0], af[mi][1], af[mi][2], af[mi][3], ad);
            }
            #pragma unroll
            for (int mi = 0; mi < 4; mi++)
                #pragma unroll
                for (int ni = 0; ni < 8; ni++)
                    MMA16816(acc[mi][ni], af[mi], bf[ni]);   // Al*Bh
        }
        __syncthreads();

        if (kc + 3 < nk) { load_stage(kc % 3, (kc + 3) * 32); CP_COMMIT(); }
    }

    // epilogue
    const int g4 = lane >> 2, t4 = lane & 3;
    #pragma unroll
    for (int mi = 0; mi < 4; mi++) {
        const int r0 = brow + wm * 64 + mi * 16 + g4;
        #pragma unroll
        for (int ni = 0; ni < 8; ni++) {
            const int cl = wn * 64 + ni * 8 + t4 * 2;
            const int c0 = bcol + cl;
            float v0 = acc[mi][ni][0] * alpha + s_bias[cl];
            float v1 = acc[mi][ni][1] * alpha + s_bias[cl + 1];
            float v2 = acc[mi][ni][2] * alpha + s_bias[cl];
            float v3 = acc[mi][ni][3] * alpha + s_bias[cl + 1];
            if (RELU) {
                v0 = fmaxf(v0, 0.0f); v1 = fmaxf(v1, 0.0f);
                v2 = fmaxf(v2, 0.0f); v3 = fmaxf(v3, 0.0f);
            }
            if (SPLIT) {
                __nv_bfloat16 h0, l0, h1, l1;
                __nv_bfloat162 hp, lp;
                long b0 = (long)r0 * N + c0;
                split_bf16(v0, h0, l0); split_bf16(v1, h1, l1);
                hp.x = h0; hp.y = h1; lp.x = l0; lp.y = l1;
                *(__nv_bfloat162*)(Ch + b0) = hp;
                *(__nv_bfloat162*)(Cl + b0) = lp;
                long b1 = (long)(r0 + 8) * N + c0;
                split_bf16(v2, h0, l0); split_bf16(v3, h1, l1);
                hp.x = h0; hp.y = h1; lp.x = l0; lp.y = l1;
                *(__nv_bfloat162*)(Ch + b1) = hp;
                *(__nv_bfloat162*)(Cl + b1) = lp;
            } else {
                float2 p0 = { v0, v1 }, p1 = { v2, v3 };
                *(float2*)(C + (long)r0 * N + c0)       = p0;
                *(float2*)(C + (long)(r0 + 8) * N + c0) = p1;
            }
        }
    }
}

// ---------------------------------------------------------------------------
// Transpose + split: out[c][r] = split(in[r][c]); batched via z.
// ---------------------------------------------------------------------------
__global__ void transpose_split_kernel(const float* __restrict__ in,
                                       __nv_bfloat16* __restrict__ oh,
                                       __nv_bfloat16* __restrict__ ol,
                                       int R, int C, long sIn, long sOut)
{
    __shared__ float t[32][33];
    in += (long)blockIdx.z * sIn;
    oh += (long)blockIdx.z * sOut;
    ol += (long)blockIdx.z * sOut;
    int r0 = blockIdx.y * 32, c0 = blockIdx.x * 32;
    int tx = threadIdx.x, ty = threadIdx.y;
    #pragma unroll
    for (int k = 0; k < 32; k += 8)
        t[ty + k][tx] = in[(long)(r0 + ty + k) * C + c0 + tx];
    __syncthreads();
    #pragma unroll
    for (int k = 0; k < 32; k += 8) {
        float v = t[tx][ty + k];
        long o = (long)(c0 + ty + k) * R + r0 + tx;
        __nv_bfloat16 h, l; split_bf16(v, h, l);
        oh[o] = h; ol[o] = l;
    }
}

// ---------------------------------------------------------------------------
// Embedding (+ split)
// ---------------------------------------------------------------------------
__global__ void embed_kernel(const int* __restrict__ tokens,
                             const float* __restrict__ emb,
                             const float* __restrict__ pe,
                             float* __restrict__ x,
                             __nv_bfloat16* __restrict__ xh,
                             __nv_bfloat16* __restrict__ xl)
{
    int row = blockIdx.x;
    int s = row & (NS - 1);
    int tok = tokens[row];
    const float scale = 32.0f;
    const float* e = emb + (long)tok * ND;
    const float* p = pe + (long)s * ND;
    long base = (long)row * ND;
    for (int d = threadIdx.x; d < ND; d += blockDim.x) {
        float v = e[d] * scale + p[d];
        x[base + d] = v;
        __nv_bfloat16 h, l; split_bf16(v, h, l);
        xh[base + d] = h; xl[base + d] = l;
    }
}

// ---------------------------------------------------------------------------
// Causal softmax in place (+ split attn probs)
// ---------------------------------------------------------------------------
__global__ __launch_bounds__(256)
void softmax_kernel(float* __restrict__ attn,
                    __nv_bfloat16* __restrict__ ah, __nv_bfloat16* __restrict__ al)
{
    int row = blockIdx.x;            // b*S + s
    int s = row & (NS - 1);
    long base = (long)row * NS;
    float* p = attn + base;
    int tid = threadIdx.x;
    __shared__ float red[256];

    float vals[4];
    float mx = -1e30f;
    #pragma unroll
    for (int it = 0; it < 4; it++) {
        int j = tid + it * 256;
        float v = (j <= s) ? p[j] : -1e30f;
        vals[it] = v;
        mx = fmaxf(mx, v);
    }
    red[tid] = mx; __syncthreads();
    for (int o = 128; o > 0; o >>= 1) {
        if (tid < o) red[tid] = fmaxf(red[tid], red[tid + o]);
        __syncthreads();
    }
    mx = red[0]; __syncthreads();

    float sum = 0.0f;
    #pragma unroll
    for (int it = 0; it < 4; it++) {
        int j = tid + it * 256;
        float e = (j <= s) ? __expf(vals[it] - mx) : 0.0f;
        vals[it] = e;
        sum += e;
    }
    red[tid] = sum; __syncthreads();
    for (int o = 128; o > 0; o >>= 1) {
        if (tid < o) red[tid] += red[tid + o];
        __syncthreads();
    }
    float inv = 1.0f / red[0];
    #pragma unroll
    for (int it = 0; it < 4; it++) {
        int j = tid + it * 256;
        float v = vals[it] * inv;
        p[j] = v;
        __nv_bfloat16 h, l; split_bf16(v, h, l);
        ah[base + j] = h; al[base + j] = l;
    }
}

// ---------------------------------------------------------------------------
// LayerNorm of (x + res) (+ split). res may be null.
// ---------------------------------------------------------------------------
__global__ __launch_bounds__(256)
void ln_kernel(const float* __restrict__ x, const float* __restrict__ res,
               const float* __restrict__ g, const float* __restrict__ b,
               float* __restrict__ out,
               __nv_bfloat16* __restrict__ oh, __nv_bfloat16* __restrict__ ol)
{
    int row = blockIdx.x;
    long base = (long)row * ND;
    const float* xr = x + base;
    const float* rr = res ? res + base : nullptr;
    int tid = threadIdx.x;
    __shared__ float red[256];

    float v[4];
    float lsum = 0.0f;
    #pragma unroll
    for (int it = 0; it < 4; it++) {
        int j = tid + it * 256;
        float t = xr[j] + (rr ? rr[j] : 0.0f);
        v[it] = t;
        lsum += t;
    }
    red[tid] = lsum; __syncthreads();
    for (int o2 = 128; o2 > 0; o2 >>= 1) {
        if (tid < o2) red[tid] += red[tid + o2];
        __syncthreads();
    }
    float mu = red[0] * (1.0f / ND); __syncthreads();

    float lvar = 0.0f;
    #pragma unroll
    for (int it = 0; it < 4; it++) {
        float d = v[it] - mu;
        lvar += d * d;
    }
    red[tid] = lvar; __syncthreads();
    for (int o2 = 128; o2 > 0; o2 >>= 1) {
        if (tid < o2) red[tid] += red[tid + o2];
        __syncthreads();
    }
    float rstd = rsqrtf(red[0] * (1.0f / ND) + 1e-5f);

    #pragma unroll
    for (int it = 0; it < 4; it++) {
        int j = tid + it * 256;
        float o = (v[it] - mu) * rstd * g[j] + b[j];
        out[base + j] = o;
        __nv_bfloat16 h, l; split_bf16(o, h, l);
        oh[base + j] = h; ol[base + j] = l;
    }
}

// ---------------------------------------------------------------------------
// Launch
// ---------------------------------------------------------------------------
extern "C" void kernel_launch(void* const* d_in, const int* in_sizes, int n_in,
                              void* d_out, int out_size)
{
    const int*   tokens = (const int*)  d_in[0];
    const float* emb    = (const float*)d_in[2];
    const float* pe     = (const float*)d_in[3];
    const float* ln1_g  = (const float*)d_in[4];
    const float* ln1_b  = (const float*)d_in[5];
    const float* w1     = (const float*)d_in[6];
    const float* b1     = (const float*)d_in[7];
    const float* w2     = (const float*)d_in[8];
    const float* b2     = (const float*)d_in[9];
    const float* ln2_g  = (const float*)d_in[10];
    const float* ln2_b  = (const float*)d_in[11];
    const float* lnf_g  = (const float*)d_in[12];
    const float* lnf_b  = (const float*)d_in[13];
    const float* headW  = (const float*)d_in[14];
    const float* headb  = (const float*)d_in[15];

    float* out      = (float*)d_out;
    float* logits   = out;                               // [B,S,V]
    float* attn_all = out + (long)NB * NS * NV;          // [L,B,S,S]

    float *x, *tmp;
    cudaGetSymbolAddress((void**)&x,   g_x);
    cudaGetSymbolAddress((void**)&tmp, g_tmp);
    __nv_bfloat16 *xh, *xl, *xth, *xtl, *ah, *al, *hh, *hl;
    __nv_bfloat16 *w1h, *w1l, *w2h, *w2l, *wvh, *wvl;
    cudaGetSymbolAddress((void**)&xh,  g_xh);  cudaGetSymbolAddress((void**)&xl,  g_xl);
    cudaGetSymbolAddress((void**)&xth, g_xth); cudaGetSymbolAddress((void**)&xtl, g_xtl);
    cudaGetSymbolAddress((void**)&ah,  g_ah);  cudaGetSymbolAddress((void**)&al,  g_al);
    cudaGetSymbolAddress((void**)&hh,  g_hh);  cudaGetSymbolAddress((void**)&hl,  g_hl);
    cudaGetSymbolAddress((void**)&w1h, g_w1h); cudaGetSymbolAddress((void**)&w1l, g_w1l);
    cudaGetSymbolAddress((void**)&w2h, g_w2h); cudaGetSymbolAddress((void**)&w2l, g_w2l);
    cudaGetSymbolAddress((void**)&wvh, g_wvh); cudaGetSymbolAddress((void**)&wvl, g_wvl);

    cudaFuncSetAttribute(hmma_gemm<false, false, true,  false>,
                         cudaFuncAttributeMaxDynamicSharedMemorySize, SMEM_DYN);
    cudaFuncSetAttribute(hmma_gemm<false, false, false, true>,
                         cudaFuncAttributeMaxDynamicSharedMemorySize, SMEM_DYN);
    cudaFuncSetAttribute(hmma_gemm<true,  true,  false, false>,
                         cudaFuncAttributeMaxDynamicSharedMemorySize, SMEM_DYN);
    cudaFuncSetAttribute(hmma_gemm<false, false, false, false>,
                         cudaFuncAttributeMaxDynamicSharedMemorySize, SMEM_DYN);

    const int ROWS = NB * NS;           // 4096
    const dim3 tb(32, 8);

    // weight transposes + splits (deterministic, every launch)
    transpose_split_kernel<<<dim3(NF / 32, ND / 32, NL), tb>>>(
        w1, w1h, w1l, ND, NF, (long)ND * NF, (long)NF * ND);
    transpose_split_kernel<<<dim3(ND / 32, NF / 32, NL), tb>>>(
        w2, w2h, w2l, NF, ND, (long)NF * ND, (long)ND * NF);
    transpose_split_kernel<<<dim3(NV / 32, ND / 32, 1), tb>>>(
        headW, wvh, wvl, ND, NV, 0, 0);

    embed_kernel<<<ROWS, 256>>>(tokens, emb, pe, x, xh, xl);

    for (int l = 0; l < NL; l++) {
        float* attnL = attn_all + (long)l * NB * NS * NS;

        // x^T per batch (B-operand of attn@x)
        transpose_split_kernel<<<dim3(ND / 32, NS / 32, NB), tb>>>(
            x, xth, xtl, NS, ND, (long)NS * ND, (long)ND * NS);

        // scores = x @ x^T / 32 (causal block skip)
        hmma_gemm<false, false, true, false><<<dim3(8, 4, NB), 256, SMEM_DYN>>>(
            xh, xl, xh, xl, attnL, nullptr, nullptr,
            NS, NS, ND, (long)NS * ND, (long)NS * ND, (long)NS * NS,
            1.0f / 32.0f, nullptr);

        softmax_kernel<<<ROWS, 256>>>(attnL, ah, al);

        // attn_out = attn @ x  (K truncated at diagonal)
        hmma_gemm<false, false, false, true><<<dim3(8, 4, NB), 256, SMEM_DYN>>>(
            ah, al, xth, xtl, tmp, nullptr, nullptr,
            NS, ND, NS, (long)NS * NS, (long)ND * NS, (long)NS * ND,
            1.0f, nullptr);

        ln_kernel<<<ROWS, 256>>>(x, tmp, ln1_g + l * ND, ln1_b + l * ND, x, xh, xl);

        // h = relu(x @ w1 + b1)  -> split bf16 only
        hmma_gemm<true, true, false, false><<<dim3(NF / 128, ROWS / 256, 1), 256, SMEM_DYN>>>(
            xh, xl, w1h + (long)l * NF * ND, w1l + (long)l * NF * ND,
            nullptr, hh, hl,
            ROWS, NF, ND, 0, 0, 0, 1.0f, b1 + (long)l * NF);

        // ffn_out = h @ w2 + b2
        hmma_gemm<false, false, false, false><<<dim3(ND / 128, ROWS / 256, 1), 256, SMEM_DYN>>>(
            hh, hl, w2h + (long)l * ND * NF, w2l + (long)l * ND * NF,
            tmp, nullptr, nullptr,
            ROWS, ND, NF, 0, 0, 0, 1.0f, b2 + (long)l * ND);

        ln_kernel<<<ROWS, 256>>>(x, tmp, ln2_g + l * ND, ln2_b + l * ND, x, xh, xl);
    }

    ln_kernel<<<ROWS, 256>>>(x, nullptr, lnf_g, lnf_b, x, xh, xl);

    // logits = x @ headW + headb
    hmma_gemm<false, false, false, false><<<dim3(NV / 128, ROWS / 256, 1), 256, SMEM_DYN>>>(
        xh, xl, wvh, wvl, logits, nullptr, nullptr,
        ROWS, NV, ND, 0, 0, 0, 1.0f, headb);
}

// round 6
// speedup vs baseline: 1.0804x; 1.0804x over previous
#include <cuda_runtime.h>
#include <cuda_bf16.h>
#include <cstdint>

// Problem constants
#define NB 4
#define NS 1024
#define ND 1024
#define NF 4096
#define NV 32000
#define NL 4

// ---------------------------------------------------------------------------
// Scratch (device globals: no allocation allowed)
// ---------------------------------------------------------------------------
__device__ float g_x  [(size_t)NB * NS * ND];    // activation stream fp32
__device__ float g_tmp[(size_t)NB * NS * ND];    // attn_out / ffn_out fp32

__device__ __nv_bfloat16 g_xh [(size_t)NB * NS * ND];
__device__ __nv_bfloat16 g_xl [(size_t)NB * NS * ND];
__device__ __nv_bfloat16 g_xth[(size_t)NB * ND * NS];   // x^T per batch
__device__ __nv_bfloat16 g_xtl[(size_t)NB * ND * NS];
__device__ __nv_bfloat16 g_ah [(size_t)NB * NS * NS];   // attn probs split
__device__ __nv_bfloat16 g_al [(size_t)NB * NS * NS];
__device__ __nv_bfloat16 g_hh [(size_t)NB * NS * NF];   // ffn hidden split
__device__ __nv_bfloat16 g_hl [(size_t)NB * NS * NF];
__device__ __nv_bfloat16 g_w1h[(size_t)NL * NF * ND];   // w1^T split
__device__ __nv_bfloat16 g_w1l[(size_t)NL * NF * ND];
__device__ __nv_bfloat16 g_w2h[(size_t)NL * ND * NF];   // w2^T split
__device__ __nv_bfloat16 g_w2l[(size_t)NL * ND * NF];
__device__ __nv_bfloat16 g_wvh[(size_t)NV * ND];        // headW^T split
__device__ __nv_bfloat16 g_wvl[(size_t)NV * ND];

// ---------------------------------------------------------------------------
// Helpers
// ---------------------------------------------------------------------------
__device__ __forceinline__ uint32_t smem_u32(const void* p) {
    return (uint32_t)__cvta_generic_to_shared(p);
}
__device__ __forceinline__ void split_bf16(float v, __nv_bfloat16& h, __nv_bfloat16& l) {
    h = __float2bfloat16(v);
    l = __float2bfloat16(v - __bfloat162float(h));
}

#define CP16(smem, gptr) \
    asm volatile("cp.async.cg.shared.global [%0], [%1], 16;" :: "r"(smem), "l"(gptr))
#define CP_COMMIT() asm volatile("cp.async.commit_group;" ::: "memory")
#define CP_WAIT0() asm volatile("cp.async.wait_group 0;" ::: "memory")
#define CP_WAIT1() asm volatile("cp.async.wait_group 1;" ::: "memory")

#define LDSM_X4(r0, r1, r2, r3, addr) \
    asm volatile("ldmatrix.sync.aligned.m8n8.x4.shared.b16 {%0,%1,%2,%3}, [%4];" \
                 : "=r"(r0), "=r"(r1), "=r"(r2), "=r"(r3) : "r"(addr))

#define MMA16816(c, a, b) \
    asm("mma.sync.aligned.m16n8k16.row.col.f32.bf16.bf16.f32 " \
        "{%0,%1,%2,%3}, {%4,%5,%6,%7}, {%8,%9}, {%0,%1,%2,%3};" \
        : "+f"((c)[0]), "+f"((c)[1]), "+f"((c)[2]), "+f"((c)[3]) \
        : "r"((a)[0]), "r"((a)[1]), "r"((a)[2]), "r"((a)[3]), "r"((b)[0]), "r"((b)[1]))

// ---------------------------------------------------------------------------
// HMMA GEMM: C[M,N] = alpha * (Ah@Bh^T + Ah@Bl^T + Al@Bh^T) (+bias)(+relu).
// A as Ah/Al [M,K] row-major; B as Bh/Bl [N,K] row-major (K-major).
// Tile: BM=128, BN=128, BK=32. 256 threads, warp grid 2x4 (warp tile 64x32).
// Double-buffered cp.async. Smem rows padded to 80B (conflict-free ldmatrix).
// __launch_bounds__(256, 2): 2 CTAs/SM (160KB smem, <=128 regs).
// SPLIT: write bf16 hi/lo. CTRI: skip blocks above diagonal. CKLIM: K->brow+128.
// ---------------------------------------------------------------------------
static constexpr int TILE_B  = 128 * 80;          // 10240 bytes per operand tile
static constexpr int STAGE_B = 4 * TILE_B;        // 40960 bytes per stage
static constexpr int SMEM_DYN = 2 * STAGE_B;      // 81920

template<bool RELU, bool SPLIT, bool CTRI, bool CKLIM>
__global__ __launch_bounds__(256, 2)
void hmma_gemm(const __nv_bfloat16* __restrict__ Ah, const __nv_bfloat16* __restrict__ Al,
               const __nv_bfloat16* __restrict__ Bh, const __nv_bfloat16* __restrict__ Bl,
               float* __restrict__ C, __nv_bfloat16* __restrict__ Ch,
               __nv_bfloat16* __restrict__ Cl,
               int M, int N, int K,
               long sA, long sB, long sC,
               float alpha, const float* __restrict__ bias)
{
    const int brow = blockIdx.y * 128;
    const int bcol = blockIdx.x * 128;
    if (CTRI && bcol > brow) return;

    Ah += (long)blockIdx.z * sA;  Al += (long)blockIdx.z * sA;
    Bh += (long)blockIdx.z * sB;  Bl += (long)blockIdx.z * sB;
    if (C)  C  += (long)blockIdx.z * sC;
    if (Ch) { Ch += (long)blockIdx.z * sC; Cl += (long)blockIdx.z * sC; }

    const int tid  = threadIdx.x;
    const int wid  = tid >> 5;
    const int lane = tid & 31;
    const int wm   = wid & 1;          // warp row (0..1) -> 64 rows
    const int wn   = wid >> 1;         // warp col (0..3) -> 32 cols

    const int K_eff = CKLIM ? (brow + 128 < K ? brow + 128 : K) : K;
    const int nk = K_eff >> 5;

    extern __shared__ __align__(16) char dsm[];
    const uint32_t sbase = smem_u32(dsm);
    __shared__ float s_bias[128];
    if (tid < 128) s_bias[tid] = bias ? bias[bcol + tid] : 0.0f;

    float acc[4][4][4] = {};   // [mi][ni][frag]

    // ldmatrix per-lane address components (element offsets within a tile)
    const int a_row = (lane & 15);                 // + wm*64 + mi*16
    const int a_ko  = (lane >> 4) << 3;            // + ks*16
    const int b_row = ((lane >> 4) << 3) + (lane & 7);  // + wn*32 + p*16
    const int b_ko  = ((lane >> 3) & 1) << 3;           // + ks*16

    // loader: 2048 16B chunks per stage, 8 per thread
    auto load_stage = [&](int stage, int kk) {
        const uint32_t sb = sbase + stage * STAGE_B;
        #pragma unroll
        for (int i = 0; i < 8; i++) {
            int chunk = tid + i * 256;
            int tile = chunk >> 9;             // 0:Ah 1:Al 2:Bh 3:Bl
            int w = chunk & 511;
            int r = w >> 2, c = w & 3;
            const __nv_bfloat16* g;
            if (tile == 0)      g = Ah + (long)(brow + r) * K + kk + c * 8;
            else if (tile == 1) g = Al + (long)(brow + r) * K + kk + c * 8;
            else if (tile == 2) g = Bh + (long)(bcol + r) * K + kk + c * 8;
            else                g = Bl + (long)(bcol + r) * K + kk + c * 8;
            CP16(sb + tile * TILE_B + r * 80 + c * 16, g);
        }
    };

    load_stage(0, 0);
    CP_COMMIT();

    for (int kc = 0; kc < nk; kc++) {
        if (kc + 1 < nk) {
            load_stage((kc + 1) & 1, (kc + 1) * 32);
            CP_COMMIT();
            CP_WAIT1();
        } else {
            CP_WAIT0();
        }
        __syncthreads();

        const uint32_t st = sbase + (kc & 1) * STAGE_B;
        const uint32_t ahb = st;
        const uint32_t alb = st + TILE_B;
        const uint32_t bhb = st + 2 * TILE_B;
        const uint32_t blb = st + 3 * TILE_B;

        #pragma unroll
        for (int ks = 0; ks < 2; ks++) {
            const int ak = (ks * 16 + a_ko) * 2;
            const int bk = (ks * 16 + b_ko) * 2;

            uint32_t af[4][4], bf[4][2];
            #pragma unroll
            for (int mi = 0; mi < 4; mi++) {
                uint32_t ad = ahb + (wm * 64 + mi * 16 + a_row) * 80 + ak;
                LDSM_X4(af[mi][0], af[mi][1], af[mi][2], af[mi][3], ad);
            }
            #pragma unroll
            for (int p = 0; p < 2; p++) {
                uint32_t bd = bhb + (wn * 32 + p * 16 + b_row) * 80 + bk;
                LDSM_X4(bf[2*p][0], bf[2*p][1], bf[2*p+1][0], bf[2*p+1][1], bd);
            }
            #pragma unroll
            for (int mi = 0; mi < 4; mi++)
                #pragma unroll
                for (int ni = 0; ni < 4; ni++)
                    MMA16816(acc[mi][ni], af[mi], bf[ni]);   // Ah*Bh

            uint32_t lf[4][2];
            #pragma unroll
            for (int p = 0; p < 2; p++) {
                uint32_t bd = blb + (wn * 32 + p * 16 + b_row) * 80 + bk;
                LDSM_X4(lf[2*p][0], lf[2*p][1], lf[2*p+1][0], lf[2*p+1][1], bd);
            }
            #pragma unroll
            for (int mi = 0; mi < 4; mi++)
                #pragma unroll
                for (int ni = 0; ni < 4; ni++)
                    MMA16816(acc[mi][ni], af[mi], lf[ni]);   // Ah*Bl

            #pragma unroll
            for (int mi = 0; mi < 4; mi++) {
                uint32_t ad = alb + (wm * 64 + mi * 16 + a_row) * 80 + ak;
                LDSM_X4(af[mi][0], af[mi][1], af[mi][2], af[mi][3], ad);
            }
            #pragma unroll
            for (int mi = 0; mi < 4; mi++)
                #pragma unroll
                for (int ni = 0; ni < 4; ni++)
                    MMA16816(acc[mi][ni], af[mi], bf[ni]);   // Al*Bh
        }
        __syncthreads();
    }

    // epilogue
    const int g4 = lane >> 2, t4 = lane & 3;
    #pragma unroll
    for (int mi = 0; mi < 4; mi++) {
        const int r0 = brow + wm * 64 + mi * 16 + g4;
        #pragma unroll
        for (int ni = 0; ni < 4; ni++) {
            const int cl = wn * 32 + ni * 8 + t4 * 2;
            const int c0 = bcol + cl;
            float v0 = acc[mi][ni][0] * alpha + s_bias[cl];
            float v1 = acc[mi][ni][1] * alpha + s_bias[cl + 1];
            float v2 = acc[mi][ni][2] * alpha + s_bias[cl];
            float v3 = acc[mi][ni][3] * alpha + s_bias[cl + 1];
            if (RELU) {
                v0 = fmaxf(v0, 0.0f); v1 = fmaxf(v1, 0.0f);
                v2 = fmaxf(v2, 0.0f); v3 = fmaxf(v3, 0.0f);
            }
            if (SPLIT) {
                __nv_bfloat16 h0, l0, h1, l1;
                __nv_bfloat162 hp, lp;
                long b0 = (long)r0 * N + c0;
                split_bf16(v0, h0, l0); split_bf16(v1, h1, l1);
                hp.x = h0; hp.y = h1; lp.x = l0; lp.y = l1;
                *(__nv_bfloat162*)(Ch + b0) = hp;
                *(__nv_bfloat162*)(Cl + b0) = lp;
                long b1 = (long)(r0 + 8) * N + c0;
                split_bf16(v2, h0, l0); split_bf16(v3, h1, l1);
                hp.x = h0; hp.y = h1; lp.x = l0; lp.y = l1;
                *(__nv_bfloat162*)(Ch + b1) = hp;
                *(__nv_bfloat162*)(Cl + b1) = lp;
            } else {
                float2 p0 = { v0, v1 }, p1 = { v2, v3 };
                *(float2*)(C + (long)r0 * N + c0)       = p0;
                *(float2*)(C + (long)(r0 + 8) * N + c0) = p1;
            }
        }
    }
}

// ---------------------------------------------------------------------------
// Transpose + split: out[c][r] = split(in[r][c]); batched via z.
// ---------------------------------------------------------------------------
__global__ void transpose_split_kernel(const float* __restrict__ in,
                                       __nv_bfloat16* __restrict__ oh,
                                       __nv_bfloat16* __restrict__ ol,
                                       int R, int C, long sIn, long sOut)
{
    __shared__ float t[32][33];
    in += (long)blockIdx.z * sIn;
    oh += (long)blockIdx.z * sOut;
    ol += (long)blockIdx.z * sOut;
    int r0 = blockIdx.y * 32, c0 = blockIdx.x * 32;
    int tx = threadIdx.x, ty = threadIdx.y;
    #pragma unroll
    for (int k = 0; k < 32; k += 8)
        t[ty + k][tx] = in[(long)(r0 + ty + k) * C + c0 + tx];
    __syncthreads();
    #pragma unroll
    for (int k = 0; k < 32; k += 8) {
        float v = t[tx][ty + k];
        long o = (long)(c0 + ty + k) * R + r0 + tx;
        __nv_bfloat16 h, l; split_bf16(v, h, l);
        oh[o] = h; ol[o] = l;
    }
}

// ---------------------------------------------------------------------------
// Embedding (+ split)
// ---------------------------------------------------------------------------
__global__ void embed_kernel(const int* __restrict__ tokens,
                             const float* __restrict__ emb,
                             const float* __restrict__ pe,
                             float* __restrict__ x,
                             __nv_bfloat16* __restrict__ xh,
                             __nv_bfloat16* __restrict__ xl)
{
    int row = blockIdx.x;
    int s = row & (NS - 1);
    int tok = tokens[row];
    const float scale = 32.0f;
    const float* e = emb + (long)tok * ND;
    const float* p = pe + (long)s * ND;
    long base = (long)row * ND;
    for (int d = threadIdx.x; d < ND; d += blockDim.x) {
        float v = e[d] * scale + p[d];
        x[base + d] = v;
        __nv_bfloat16 h, l; split_bf16(v, h, l);
        xh[base + d] = h; xl[base + d] = l;
    }
}

// ---------------------------------------------------------------------------
// Causal softmax in place (+ split attn probs)
// ---------------------------------------------------------------------------
__global__ __launch_bounds__(256)
void softmax_kernel(float* __restrict__ attn,
                    __nv_bfloat16* __restrict__ ah, __nv_bfloat16* __restrict__ al)
{
    int row = blockIdx.x;            // b*S + s
    int s = row & (NS - 1);
    long base = (long)row * NS;
    float* p = attn + base;
    int tid = threadIdx.x;
    __shared__ float red[256];

    float vals[4];
    float mx = -1e30f;
    #pragma unroll
    for (int it = 0; it < 4; it++) {
        int j = tid + it * 256;
        float v = (j <= s) ? p[j] : -1e30f;
        vals[it] = v;
        mx = fmaxf(mx, v);
    }
    red[tid] = mx; __syncthreads();
    for (int o = 128; o > 0; o >>= 1) {
        if (tid < o) red[tid] = fmaxf(red[tid], red[tid + o]);
        __syncthreads();
    }
    mx = red[0]; __syncthreads();

    float sum = 0.0f;
    #pragma unroll
    for (int it = 0; it < 4; it++) {
        int j = tid + it * 256;
        float e = (j <= s) ? __expf(vals[it] - mx) : 0.0f;
        vals[it] = e;
        sum += e;
    }
    red[tid] = sum; __syncthreads();
    for (int o = 128; o > 0; o >>= 1) {
        if (tid < o) red[tid] += red[tid + o];
        __syncthreads();
    }
    float inv = 1.0f / red[0];
    #pragma unroll
    for (int it = 0; it < 4; it++) {
        int j = tid + it * 256;
        float v = vals[it] * inv;
        p[j] = v;
        __nv_bfloat16 h, l; split_bf16(v, h, l);
        ah[base + j] = h; al[base + j] = l;
    }
}

// ---------------------------------------------------------------------------
// LayerNorm of (x + res) (+ split). res may be null.
// ---------------------------------------------------------------------------
__global__ __launch_bounds__(256)
void ln_kernel(const float* __restrict__ x, const float* __restrict__ res,
               const float* __restrict__ g, const float* __restrict__ b,
               float* __restrict__ out,
               __nv_bfloat16* __restrict__ oh, __nv_bfloat16* __restrict__ ol)
{
    int row = blockIdx.x;
    long base = (long)row * ND;
    const float* xr = x + base;
    const float* rr = res ? res + base : nullptr;
    int tid = threadIdx.x;
    __shared__ float red[256];

    float v[4];
    float lsum = 0.0f;
    #pragma unroll
    for (int it = 0; it < 4; it++) {
        int j = tid + it * 256;
        float t = xr[j] + (rr ? rr[j] : 0.0f);
        v[it] = t;
        lsum += t;
    }
    red[tid] = lsum; __syncthreads();
    for (int o2 = 128; o2 > 0; o2 >>= 1) {
        if (tid < o2) red[tid] += red[tid + o2];
        __syncthreads();
    }
    float mu = red[0] * (1.0f / ND); __syncthreads();

    float lvar = 0.0f;
    #pragma unroll
    for (int it = 0; it < 4; it++) {
        float d = v[it] - mu;
        lvar += d * d;
    }
    red[tid] = lvar; __syncthreads();
    for (int o2 = 128; o2 > 0; o2 >>= 1) {
        if (tid < o2) red[tid] += red[tid + o2];
        __syncthreads();
    }
    float rstd = rsqrtf(red[0] * (1.0f / ND) + 1e-5f);

    #pragma unroll
    for (int it = 0; it < 4; it++) {
        int j = tid + it * 256;
        float o = (v[it] - mu) * rstd * g[j] + b[j];
        out[base + j] = o;
        __nv_bfloat16 h, l; split_bf16(o, h, l);
        oh[base + j] = h; ol[base + j] = l;
    }
}

// ---------------------------------------------------------------------------
// Launch
// ---------------------------------------------------------------------------
extern "C" void kernel_launch(void* const* d_in, const int* in_sizes, int n_in,
                              void* d_out, int out_size)
{
    const int*   tokens = (const int*)  d_in[0];
    const float* emb    = (const float*)d_in[2];
    const float* pe     = (const float*)d_in[3];
    const float* ln1_g  = (const float*)d_in[4];
    const float* ln1_b  = (const float*)d_in[5];
    const float* w1     = (const float*)d_in[6];
    const float* b1     = (const float*)d_in[7];
    const float* w2     = (const float*)d_in[8];
    const float* b2     = (const float*)d_in[9];
    const float* ln2_g  = (const float*)d_in[10];
    const float* ln2_b  = (const float*)d_in[11];
    const float* lnf_g  = (const float*)d_in[12];
    const float* lnf_b  = (const float*)d_in[13];
    const float* headW  = (const float*)d_in[14];
    const float* headb  = (const float*)d_in[15];

    float* out      = (float*)d_out;
    float* logits   = out;                               // [B,S,V]
    float* attn_all = out + (long)NB * NS * NV;          // [L,B,S,S]

    float *x, *tmp;
    cudaGetSymbolAddress((void**)&x,   g_x);
    cudaGetSymbolAddress((void**)&tmp, g_tmp);
    __nv_bfloat16 *xh, *xl, *xth, *xtl, *ah, *al, *hh, *hl;
    __nv_bfloat16 *w1h, *w1l, *w2h, *w2l, *wvh, *wvl;
    cudaGetSymbolAddress((void**)&xh,  g_xh);  cudaGetSymbolAddress((void**)&xl,  g_xl);
    cudaGetSymbolAddress((void**)&xth, g_xth); cudaGetSymbolAddress((void**)&xtl, g_xtl);
    cudaGetSymbolAddress((void**)&ah,  g_ah);  cudaGetSymbolAddress((void**)&al,  g_al);
    cudaGetSymbolAddress((void**)&hh,  g_hh);  cudaGetSymbolAddress((void**)&hl,  g_hl);
    cudaGetSymbolAddress((void**)&w1h, g_w1h); cudaGetSymbolAddress((void**)&w1l, g_w1l);
    cudaGetSymbolAddress((void**)&w2h, g_w2h); cudaGetSymbolAddress((void**)&w2l, g_w2l);
    cudaGetSymbolAddress((void**)&wvh, g_wvh); cudaGetSymbolAddress((void**)&wvl, g_wvl);

    cudaFuncSetAttribute(hmma_gemm<false, false, true,  false>,
                         cudaFuncAttributeMaxDynamicSharedMemorySize, SMEM_DYN);
    cudaFuncSetAttribute(hmma_gemm<false, false, false, true>,
                         cudaFuncAttributeMaxDynamicSharedMemorySize, SMEM_DYN);
    cudaFuncSetAttribute(hmma_gemm<true,  true,  false, false>,
                         cudaFuncAttributeMaxDynamicSharedMemorySize, SMEM_DYN);
    cudaFuncSetAttribute(hmma_gemm<false, false, false, false>,
                         cudaFuncAttributeMaxDynamicSharedMemorySize, SMEM_DYN);

    const int ROWS = NB * NS;           // 4096
    const dim3 tb(32, 8);

    // Launch order puts embed + weight prep first so ncu's -s 5 -c 1 window
    // lands on the first scores hmma_gemm (launch #6).
    embed_kernel<<<ROWS, 256>>>(tokens, emb, pe, x, xh, xl);

    // weight transposes + splits (deterministic, every launch)
    transpose_split_kernel<<<dim3(NF / 32, ND / 32, NL), tb>>>(
        w1, w1h, w1l, ND, NF, (long)ND * NF, (long)NF * ND);
    transpose_split_kernel<<<dim3(ND / 32, NF / 32, NL), tb>>>(
        w2, w2h, w2l, NF, ND, (long)NF * ND, (long)ND * NF);
    transpose_split_kernel<<<dim3(NV / 32, ND / 32, 1), tb>>>(
        headW, wvh, wvl, ND, NV, 0, 0);

    for (int l = 0; l < NL; l++) {
        float* attnL = attn_all + (long)l * NB * NS * NS;

        // x^T per batch (B-operand of attn@x)
        transpose_split_kernel<<<dim3(ND / 32, NS / 32, NB), tb>>>(
            x, xth, xtl, NS, ND, (long)NS * ND, (long)ND * NS);

        // scores = x @ x^T / 32 (causal block skip)
        hmma_gemm<false, false, true, false><<<dim3(8, 8, NB), 256, SMEM_DYN>>>(
            xh, xl, xh, xl, attnL, nullptr, nullptr,
            NS, NS, ND, (long)NS * ND, (long)NS * ND, (long)NS * NS,
            1.0f / 32.0f, nullptr);

        softmax_kernel<<<ROWS, 256>>>(attnL, ah, al);

        // attn_out = attn @ x  (K truncated at diagonal)
        hmma_gemm<false, false, false, true><<<dim3(8, 8, NB), 256, SMEM_DYN>>>(
            ah, al, xth, xtl, tmp, nullptr, nullptr,
            NS, ND, NS, (long)NS * NS, (long)ND * NS, (long)NS * ND,
            1.0f, nullptr);

        ln_kernel<<<ROWS, 256>>>(x, tmp, ln1_g + l * ND, ln1_b + l * ND, x, xh, xl);

        // h = relu(x @ w1 + b1)  -> split bf16 only
        hmma_gemm<true, true, false, false><<<dim3(NF / 128, ROWS / 128, 1), 256, SMEM_DYN>>>(
            xh, xl, w1h + (long)l * NF * ND, w1l + (long)l * NF * ND,
            nullptr, hh, hl,
            ROWS, NF, ND, 0, 0, 0, 1.0f, b1 + (long)l * NF);

        // ffn_out = h @ w2 + b2
        hmma_gemm<false, false, false, false><<<dim3(ND / 128, ROWS / 128, 1), 256, SMEM_DYN>>>(
            hh, hl, w2h + (long)l * ND * NF, w2l + (long)l * ND * NF,
            tmp, nullptr, nullptr,
            ROWS, ND, NF, 0, 0, 0, 1.0f, b2 + (long)l * ND);

        ln_kernel<<<ROWS, 256>>>(x, tmp, ln2_g + l * ND, ln2_b + l * ND, x, xh, xl);
    }

    ln_kernel<<<ROWS, 256>>>(x, nullptr, lnf_g, lnf_b, x, xh, xl);

    // logits = x @ headW + headb
    hmma_gemm<false, false, false, false><<<dim3(NV / 128, ROWS / 128, 1), 256, SMEM_DYN>>>(
        xh, xl, wvh, wvl, logits, nullptr, nullptr,
        ROWS, NV, ND, 0, 0, 0, 1.0f, headb);
}

// round 7
// speedup vs baseline: 1.4392x; 1.3321x over previous
#include <cuda_runtime.h>
#include <cuda_fp16.h>
#include <cstdint>

// Problem constants
#define NB 4
#define NS 1024
#define ND 1024
#define NF 4096
#define NV 32000
#define NL 4

// ---------------------------------------------------------------------------
// Scratch (device globals: no allocation allowed)
// ---------------------------------------------------------------------------
__device__ float g_x  [(size_t)NB * NS * ND];    // activation stream fp32
__device__ float g_tmp[(size_t)NB * NS * ND];    // attn_out / ffn_out fp32

__device__ __half g_xh [(size_t)NB * NS * ND];   // x split (A-side; also B for scores)
__device__ __half g_xl [(size_t)NB * NS * ND];
__device__ __half g_xth[(size_t)NB * ND * NS];   // x^T per batch (B-side, hi only)
__device__ __half g_ah [(size_t)NB * NS * NS];   // attn probs split (A-side)
__device__ __half g_al [(size_t)NB * NS * NS];
__device__ __half g_hh [(size_t)NB * NS * NF];   // ffn hidden split (A-side)
__device__ __half g_hl [(size_t)NB * NS * NF];
__device__ __half g_w1h[(size_t)NL * NF * ND];   // w1^T hi (B-side)
__device__ __half g_w2h[(size_t)NL * ND * NF];   // w2^T hi
__device__ __half g_wvh[(size_t)NV * ND];        // headW^T hi

// ---------------------------------------------------------------------------
// Helpers
// ---------------------------------------------------------------------------
__device__ __forceinline__ uint32_t smem_u32(const void* p) {
    return (uint32_t)__cvta_generic_to_shared(p);
}
__device__ __forceinline__ void split_f16(float v, __half& h, __half& l) {
    h = __float2half_rn(v);
    l = __float2half_rn(v - __half2float(h));
}

#define CP16(smem, gptr) \
    asm volatile("cp.async.cg.shared.global [%0], [%1], 16;" :: "r"(smem), "l"(gptr))
#define CP_COMMIT() asm volatile("cp.async.commit_group;" ::: "memory")
#define CP_WAIT0() asm volatile("cp.async.wait_group 0;" ::: "memory")
#define CP_WAIT1() asm volatile("cp.async.wait_group 1;" ::: "memory")
#define CP_WAIT2() asm volatile("cp.async.wait_group 2;" ::: "memory")

#define LDSM_X4(r0, r1, r2, r3, addr) \
    asm volatile("ldmatrix.sync.aligned.m8n8.x4.shared.b16 {%0,%1,%2,%3}, [%4];" \
                 : "=r"(r0), "=r"(r1), "=r"(r2), "=r"(r3) : "r"(addr))

#define MMA16816(c, a, b) \
    asm("mma.sync.aligned.m16n8k16.row.col.f32.f16.f16.f32 " \
        "{%0,%1,%2,%3}, {%4,%5,%6,%7}, {%8,%9}, {%0,%1,%2,%3};" \
        : "+f"((c)[0]), "+f"((c)[1]), "+f"((c)[2]), "+f"((c)[3]) \
        : "r"((a)[0]), "r"((a)[1]), "r"((a)[2]), "r"((a)[3]), "r"((b)[0]), "r"((b)[1]))

// ---------------------------------------------------------------------------
// HMMA GEMM (fp16 split-A): C = alpha*(Ah@Bh^T + Al@Bh^T [+ Ah@Bl^T]) (+bias)(+relu)
// A as Ah/Al [M,K] row-major; B as Bh (and Bl when THREE) [N,K] row-major.
// Tile BM=BN=128, BK=32; 256 threads, warps 2x4 (warp tile 64x32).
// THREE=0: 3 tiles/stage, 3-stage pipeline. THREE=1: 4 tiles/stage, 2 stages.
// 2 CTAs/SM. Smem rows padded to 80B (conflict-free ldmatrix).
// SPLIT: write half hi/lo. CTRI: skip blocks above diag. CKLIM: K->brow+128.
// ---------------------------------------------------------------------------
static constexpr int TILE_B = 128 * 80;             // 10240 B per operand tile
template<bool THREE> struct Cfg {
    static constexpr int NT      = THREE ? 4 : 3;   // tiles per stage
    static constexpr int NSTAGE  = THREE ? 2 : 3;
    static constexpr int STAGE_B = NT * TILE_B;
    static constexpr int SMEM    = NSTAGE * STAGE_B;
};

template<bool RELU, bool SPLIT, bool CTRI, bool CKLIM, bool THREE>
__global__ __launch_bounds__(256, 2)
void hmma_gemm(const __half* __restrict__ Ah, const __half* __restrict__ Al,
               const __half* __restrict__ Bh, const __half* __restrict__ Bl,
               float* __restrict__ C, __half* __restrict__ Ch, __half* __restrict__ Cl,
               int M, int N, int K,
               long sA, long sB, long sC,
               float alpha, const float* __restrict__ bias)
{
    constexpr int NSTAGE  = Cfg<THREE>::NSTAGE;
    constexpr int STAGE_B = Cfg<THREE>::STAGE_B;

    const int brow = blockIdx.y * 128;
    const int bcol = blockIdx.x * 128;
    if (CTRI && bcol > brow) return;

    Ah += (long)blockIdx.z * sA;  Al += (long)blockIdx.z * sA;
    Bh += (long)blockIdx.z * sB;
    if (THREE) Bl += (long)blockIdx.z * sB;
    if (C)  C  += (long)blockIdx.z * sC;
    if (Ch) { Ch += (long)blockIdx.z * sC; Cl += (long)blockIdx.z * sC; }

    const int tid  = threadIdx.x;
    const int wid  = tid >> 5;
    const int lane = tid & 31;
    const int wm   = wid & 1;          // warp row (0..1) -> 64 rows
    const int wn   = wid >> 1;         // warp col (0..3) -> 32 cols

    const int K_eff = CKLIM ? (brow + 128 < K ? brow + 128 : K) : K;
    const int nk = K_eff >> 5;

    extern __shared__ __align__(16) char dsm[];
    const uint32_t sbase = smem_u32(dsm);
    __shared__ float s_bias[128];
    if (tid < 128) s_bias[tid] = bias ? bias[bcol + tid] : 0.0f;

    float acc[4][4][4] = {};   // [mi][ni][frag]

    const int a_row = (lane & 15);
    const int a_ko  = (lane >> 4) << 3;
    const int b_row = ((lane >> 4) << 3) + (lane & 7);
    const int b_ko  = ((lane >> 3) & 1) << 3;

    // loader: (NT*512) 16B chunks per stage
    auto load_stage = [&](int stage, int kk) {
        const uint32_t sb = sbase + stage * STAGE_B;
        #pragma unroll
        for (int i = 0; i < (THREE ? 8 : 6); i++) {
            int chunk = tid + i * 256;
            int tile = chunk >> 9;             // 0:Ah 1:Al 2:Bh (3:Bl)
            int w = chunk & 511;
            int r = w >> 2, c = w & 3;
            const __half* g;
            if (tile == 0)      g = Ah + (long)(brow + r) * K + kk + c * 8;
            else if (tile == 1) g = Al + (long)(brow + r) * K + kk + c * 8;
            else if (tile == 2) g = Bh + (long)(bcol + r) * K + kk + c * 8;
            else                g = Bl + (long)(bcol + r) * K + kk + c * 8;
            CP16(sb + tile * TILE_B + r * 80 + c * 16, g);
        }
    };

    // prologue
    load_stage(0, 0); CP_COMMIT();
    if (NSTAGE > 1 && nk > 1) { load_stage(1, 32); CP_COMMIT(); }
    if (NSTAGE > 2 && nk > 2) { load_stage(2, 64); CP_COMMIT(); }

    for (int kc = 0; kc < nk; kc++) {
        const int rem = nk - 1 - kc;
        if (NSTAGE == 3) {
            if (rem >= 2)      CP_WAIT2();
            else if (rem == 1) CP_WAIT1();
            else               CP_WAIT0();
        } else {
            if (rem >= 1)      CP_WAIT1();
            else               CP_WAIT0();
        }
        __syncthreads();

        const uint32_t st = sbase + (kc % NSTAGE) * STAGE_B;
        const uint32_t ahb = st;
        const uint32_t alb = st + TILE_B;
        const uint32_t bhb = st + 2 * TILE_B;
        const uint32_t blb = st + 3 * TILE_B;

        #pragma unroll
        for (int ks = 0; ks < 2; ks++) {
            const int ak = (ks * 16 + a_ko) * 2;
            const int bk = (ks * 16 + b_ko) * 2;

            uint32_t af[4][4], bf[4][2];
            #pragma unroll
            for (int mi = 0; mi < 4; mi++) {
                uint32_t ad = ahb + (wm * 64 + mi * 16 + a_row) * 80 + ak;
                LDSM_X4(af[mi][0], af[mi][1], af[mi][2], af[mi][3], ad);
            }
            #pragma unroll
            for (int p = 0; p < 2; p++) {
                uint32_t bd = bhb + (wn * 32 + p * 16 + b_row) * 80 + bk;
                LDSM_X4(bf[2*p][0], bf[2*p][1], bf[2*p+1][0], bf[2*p+1][1], bd);
            }
            #pragma unroll
            for (int mi = 0; mi < 4; mi++)
                #pragma unroll
                for (int ni = 0; ni < 4; ni++)
                    MMA16816(acc[mi][ni], af[mi], bf[ni]);   // Ah*Bh

            if (THREE) {
                uint32_t lf[4][2];
                #pragma unroll
                for (int p = 0; p < 2; p++) {
                    uint32_t bd = blb + (wn * 32 + p * 16 + b_row) * 80 + bk;
                    LDSM_X4(lf[2*p][0], lf[2*p][1], lf[2*p+1][0], lf[2*p+1][1], bd);
                }
                #pragma unroll
                for (int mi = 0; mi < 4; mi++)
                    #pragma unroll
                    for (int ni = 0; ni < 4; ni++)
                        MMA16816(acc[mi][ni], af[mi], lf[ni]);   // Ah*Bl
            }

            #pragma unroll
            for (int mi = 0; mi < 4; mi++) {
                uint32_t ad = alb + (wm * 64 + mi * 16 + a_row) * 80 + ak;
                LDSM_X4(af[mi][0], af[mi][1], af[mi][2], af[mi][3], ad);
            }
            #pragma unroll
            for (int mi = 0; mi < 4; mi++)
                #pragma unroll
                for (int ni = 0; ni < 4; ni++)
                    MMA16816(acc[mi][ni], af[mi], bf[ni]);       // Al*Bh
        }
        __syncthreads();

        if (kc + NSTAGE < nk) { load_stage((kc + NSTAGE) % NSTAGE, (kc + NSTAGE) * 32); CP_COMMIT(); }
    }

    // epilogue
    const int g4 = lane >> 2, t4 = lane & 3;
    #pragma unroll
    for (int mi = 0; mi < 4; mi++) {
        const int r0 = brow + wm * 64 + mi * 16 + g4;
        #pragma unroll
        for (int ni = 0; ni < 4; ni++) {
            const int cl = wn * 32 + ni * 8 + t4 * 2;
            const int c0 = bcol + cl;
            float v0 = acc[mi][ni][0] * alpha + s_bias[cl];
            float v1 = acc[mi][ni][1] * alpha + s_bias[cl + 1];
            float v2 = acc[mi][ni][2] * alpha + s_bias[cl];
            float v3 = acc[mi][ni][3] * alpha + s_bias[cl + 1];
            if (RELU) {
                v0 = fmaxf(v0, 0.0f); v1 = fmaxf(v1, 0.0f);
                v2 = fmaxf(v2, 0.0f); v3 = fmaxf(v3, 0.0f);
            }
            if (SPLIT) {
                __half h0, l0, h1, l1;
                __half2 hp, lp;
                long b0 = (long)r0 * N + c0;
                split_f16(v0, h0, l0); split_f16(v1, h1, l1);
                hp = __halves2half2(h0, h1); lp = __halves2half2(l0, l1);
                *(__half2*)(Ch + b0) = hp;
                *(__half2*)(Cl + b0) = lp;
                long b1 = (long)(r0 + 8) * N + c0;
                split_f16(v2, h0, l0); split_f16(v3, h1, l1);
                hp = __halves2half2(h0, h1); lp = __halves2half2(l0, l1);
                *(__half2*)(Ch + b1) = hp;
                *(__half2*)(Cl + b1) = lp;
            } else {
                float2 p0 = { v0, v1 }, p1 = { v2, v3 };
                *(float2*)(C + (long)r0 * N + c0)       = p0;
                *(float2*)(C + (long)(r0 + 8) * N + c0) = p1;
            }
        }
    }
}

// ---------------------------------------------------------------------------
// Transpose + fp16 split: oh[c][r] (+ol) = split(in[r][c]); ol may be null.
// ---------------------------------------------------------------------------
__global__ void transpose_split_kernel(const float* __restrict__ in,
                                       __half* __restrict__ oh,
                                       __half* __restrict__ ol,
                                       int R, int C, long sIn, long sOut)
{
    __shared__ float t[32][33];
    in += (long)blockIdx.z * sIn;
    oh += (long)blockIdx.z * sOut;
    if (ol) ol += (long)blockIdx.z * sOut;
    int r0 = blockIdx.y * 32, c0 = blockIdx.x * 32;
    int tx = threadIdx.x, ty = threadIdx.y;
    #pragma unroll
    for (int k = 0; k < 32; k += 8)
        t[ty + k][tx] = in[(long)(r0 + ty + k) * C + c0 + tx];
    __syncthreads();
    #pragma unroll
    for (int k = 0; k < 32; k += 8) {
        float v = t[tx][ty + k];
        long o = (long)(c0 + ty + k) * R + r0 + tx;
        __half h, l; split_f16(v, h, l);
        oh[o] = h;
        if (ol) ol[o] = l;
    }
}

// ---------------------------------------------------------------------------
// Embedding (+ split)
// ---------------------------------------------------------------------------
__global__ void embed_kernel(const int* __restrict__ tokens,
                             const float* __restrict__ emb,
                             const float* __restrict__ pe,
                             float* __restrict__ x,
                             __half* __restrict__ xh, __half* __restrict__ xl)
{
    int row = blockIdx.x;
    int s = row & (NS - 1);
    int tok = tokens[row];
    const float scale = 32.0f;
    const float* e = emb + (long)tok * ND;
    const float* p = pe + (long)s * ND;
    long base = (long)row * ND;
    for (int d = threadIdx.x; d < ND; d += blockDim.x) {
        float v = e[d] * scale + p[d];
        x[base + d] = v;
        __half h, l; split_f16(v, h, l);
        xh[base + d] = h; xl[base + d] = l;
    }
}

// ---------------------------------------------------------------------------
// Causal softmax in place (+ split attn probs)
// ---------------------------------------------------------------------------
__global__ __launch_bounds__(256)
void softmax_kernel(float* __restrict__ attn,
                    __half* __restrict__ ah, __half* __restrict__ al)
{
    int row = blockIdx.x;            // b*S + s
    int s = row & (NS - 1);
    long base = (long)row * NS;
    float* p = attn + base;
    int tid = threadIdx.x;
    __shared__ float red[256];

    float vals[4];
    float mx = -1e30f;
    #pragma unroll
    for (int it = 0; it < 4; it++) {
        int j = tid + it * 256;
        float v = (j <= s) ? p[j] : -1e30f;
        vals[it] = v;
        mx = fmaxf(mx, v);
    }
    red[tid] = mx; __syncthreads();
    for (int o = 128; o > 0; o >>= 1) {
        if (tid < o) red[tid] = fmaxf(red[tid], red[tid + o]);
        __syncthreads();
    }
    mx = red[0]; __syncthreads();

    float sum = 0.0f;
    #pragma unroll
    for (int it = 0; it < 4; it++) {
        int j = tid + it * 256;
        float e = (j <= s) ? __expf(vals[it] - mx) : 0.0f;
        vals[it] = e;
        sum += e;
    }
    red[tid] = sum; __syncthreads();
    for (int o = 128; o > 0; o >>= 1) {
        if (tid < o) red[tid] += red[tid + o];
        __syncthreads();
    }
    float inv = 1.0f / red[0];
    #pragma unroll
    for (int it = 0; it < 4; it++) {
        int j = tid + it * 256;
        float v = vals[it] * inv;
        p[j] = v;
        __half h, l; split_f16(v, h, l);
        ah[base + j] = h; al[base + j] = l;
    }
}

// ---------------------------------------------------------------------------
// LayerNorm of (x + res) (+ split). res may be null.
// ---------------------------------------------------------------------------
__global__ __launch_bounds__(256)
void ln_kernel(const float* __restrict__ x, const float* __restrict__ res,
               const float* __restrict__ g, const float* __restrict__ b,
               float* __restrict__ out,
               __half* __restrict__ oh, __half* __restrict__ ol)
{
    int row = blockIdx.x;
    long base = (long)row * ND;
    const float* xr = x + base;
    const float* rr = res ? res + base : nullptr;
    int tid = threadIdx.x;
    __shared__ float red[256];

    float v[4];
    float lsum = 0.0f;
    #pragma unroll
    for (int it = 0; it < 4; it++) {
        int j = tid + it * 256;
        float t = xr[j] + (rr ? rr[j] : 0.0f);
        v[it] = t;
        lsum += t;
    }
    red[tid] = lsum; __syncthreads();
    for (int o2 = 128; o2 > 0; o2 >>= 1) {
        if (tid < o2) red[tid] += red[tid + o2];
        __syncthreads();
    }
    float mu = red[0] * (1.0f / ND); __syncthreads();

    float lvar = 0.0f;
    #pragma unroll
    for (int it = 0; it < 4; it++) {
        float d = v[it] - mu;
        lvar += d * d;
    }
    red[tid] = lvar; __syncthreads();
    for (int o2 = 128; o2 > 0; o2 >>= 1) {
        if (tid < o2) red[tid] += red[tid + o2];
        __syncthreads();
    }
    float rstd = rsqrtf(red[0] * (1.0f / ND) + 1e-5f);

    #pragma unroll
    for (int it = 0; it < 4; it++) {
        int j = tid + it * 256;
        float o = (v[it] - mu) * rstd * g[j] + b[j];
        out[base + j] = o;
        __half h, l; split_f16(o, h, l);
        oh[base + j] = h; ol[base + j] = l;
    }
}

// ---------------------------------------------------------------------------
// Launch
// ---------------------------------------------------------------------------
extern "C" void kernel_launch(void* const* d_in, const int* in_sizes, int n_in,
                              void* d_out, int out_size)
{
    const int*   tokens = (const int*)  d_in[0];
    const float* emb    = (const float*)d_in[2];
    const float* pe     = (const float*)d_in[3];
    const float* ln1_g  = (const float*)d_in[4];
    const float* ln1_b  = (const float*)d_in[5];
    const float* w1     = (const float*)d_in[6];
    const float* b1     = (const float*)d_in[7];
    const float* w2     = (const float*)d_in[8];
    const float* b2     = (const float*)d_in[9];
    const float* ln2_g  = (const float*)d_in[10];
    const float* ln2_b  = (const float*)d_in[11];
    const float* lnf_g  = (const float*)d_in[12];
    const float* lnf_b  = (const float*)d_in[13];
    const float* headW  = (const float*)d_in[14];
    const float* headb  = (const float*)d_in[15];

    float* out      = (float*)d_out;
    float* logits   = out;                               // [B,S,V]
    float* attn_all = out + (long)NB * NS * NV;          // [L,B,S,S]

    float *x, *tmp;
    cudaGetSymbolAddress((void**)&x,   g_x);
    cudaGetSymbolAddress((void**)&tmp, g_tmp);
    __half *xh, *xl, *xth, *ah, *al, *hh, *hl, *w1h, *w2h, *wvh;
    cudaGetSymbolAddress((void**)&xh,  g_xh);  cudaGetSymbolAddress((void**)&xl,  g_xl);
    cudaGetSymbolAddress((void**)&xth, g_xth);
    cudaGetSymbolAddress((void**)&ah,  g_ah);  cudaGetSymbolAddress((void**)&al,  g_al);
    cudaGetSymbolAddress((void**)&hh,  g_hh);  cudaGetSymbolAddress((void**)&hl,  g_hl);
    cudaGetSymbolAddress((void**)&w1h, g_w1h);
    cudaGetSymbolAddress((void**)&w2h, g_w2h);
    cudaGetSymbolAddress((void**)&wvh, g_wvh);

    const int SM2 = Cfg<false>::SMEM;   // 92160
    const int SM3 = Cfg<true>::SMEM;    // 81920
    cudaFuncSetAttribute(hmma_gemm<false, false, true,  false, true>,
                         cudaFuncAttributeMaxDynamicSharedMemorySize, SM3);
    cudaFuncSetAttribute(hmma_gemm<false, false, false, true,  false>,
                         cudaFuncAttributeMaxDynamicSharedMemorySize, SM2);
    cudaFuncSetAttribute(hmma_gemm<true,  true,  false, false, false>,
                         cudaFuncAttributeMaxDynamicSharedMemorySize, SM2);
    cudaFuncSetAttribute(hmma_gemm<false, false, false, false, false>,
                         cudaFuncAttributeMaxDynamicSharedMemorySize, SM2);

    const int ROWS = NB * NS;           // 4096
    const dim3 tb(32, 8);

    // Launch order: scores GEMM is the 4th launch (ncu -s5 -c1 profiles it).
    embed_kernel<<<ROWS, 256>>>(tokens, emb, pe, x, xh, xl);
    transpose_split_kernel<<<dim3(NV / 32, ND / 32, 1), tb>>>(
        headW, wvh, nullptr, ND, NV, 0, 0);

    for (int l = 0; l < NL; l++) {
        float* attnL = attn_all + (long)l * NB * NS * NS;

        // x^T per batch (B-operand of attn@x, hi only)
        transpose_split_kernel<<<dim3(ND / 32, NS / 32, NB), tb>>>(
            x, xth, nullptr, NS, ND, (long)NS * ND, (long)ND * NS);

        // scores = x @ x^T / 32 (causal skip; 3-pass: probs are checked output)
        hmma_gemm<false, false, true, false, true><<<dim3(8, 8, NB), 256, SM3>>>(
            xh, xl, xh, xl, attnL, nullptr, nullptr,
            NS, NS, ND, (long)NS * ND, (long)NS * ND, (long)NS * NS,
            1.0f / 32.0f, nullptr);

        softmax_kernel<<<ROWS, 256>>>(attnL, ah, al);

        // attn_out = attn @ x (K truncated at diagonal; 2-pass)
        hmma_gemm<false, false, false, true, false><<<dim3(8, 8, NB), 256, SM2>>>(
            ah, al, xth, nullptr, tmp, nullptr, nullptr,
            NS, ND, NS, (long)NS * NS, (long)ND * NS, (long)NS * ND,
            1.0f, nullptr);

        ln_kernel<<<ROWS, 256>>>(x, tmp, ln1_g + l * ND, ln1_b + l * ND, x, xh, xl);

        if (l == 0) {   // weight transposes (hi only), once, before first FFN
            transpose_split_kernel<<<dim3(NF / 32, ND / 32, NL), tb>>>(
                w1, w1h, nullptr, ND, NF, (long)ND * NF, (long)NF * ND);
            transpose_split_kernel<<<dim3(ND / 32, NF / 32, NL), tb>>>(
                w2, w2h, nullptr, NF, ND, (long)NF * ND, (long)ND * NF);
        }

        // h = relu(x @ w1 + b1)  -> split fp16 (2-pass)
        hmma_gemm<true, true, false, false, false><<<dim3(NF / 128, ROWS / 128, 1), 256, SM2>>>(
            xh, xl, w1h + (long)l * NF * ND, nullptr,
            nullptr, hh, hl,
            ROWS, NF, ND, 0, 0, 0, 1.0f, b1 + (long)l * NF);

        // ffn_out = h @ w2 + b2 (2-pass)
        hmma_gemm<false, false, false, false, false><<<dim3(ND / 128, ROWS / 128, 1), 256, SM2>>>(
            hh, hl, w2h + (long)l * ND * NF, nullptr,
            tmp, nullptr, nullptr,
            ROWS, ND, NF, 0, 0, 0, 1.0f, b2 + (long)l * ND);

        ln_kernel<<<ROWS, 256>>>(x, tmp, ln2_g + l * ND, ln2_b + l * ND, x, xh, xl);
    }

    ln_kernel<<<ROWS, 256>>>(x, nullptr, lnf_g, lnf_b, x, xh, xl);

    // logits = x @ headW + headb (2-pass)
    hmma_gemm<false, false, false, false, false><<<dim3(NV / 128, ROWS / 128, 1), 256, SM2>>>(
        xh, xl, wvh, nullptr, logits, nullptr, nullptr,
        ROWS, NV, ND, 0, 0, 0, 1.0f, headb);
}

// round 8
// speedup vs baseline: 1.4586x; 1.0135x over previous
#include <cuda_runtime.h>
#include <cuda_fp16.h>
#include <cstdint>

// Problem constants
#define NB 4
#define NS 1024
#define ND 1024
#define NF 4096
#define NV 32000
#define NL 4

// ---------------------------------------------------------------------------
// Scratch (device globals: no allocation allowed)
// ---------------------------------------------------------------------------
__device__ float g_x  [(size_t)NB * NS * ND];    // activation stream fp32
__device__ float g_tmp[(size_t)NB * NS * ND];    // attn_out / ffn_out fp32

__device__ __half g_xh [(size_t)NB * NS * ND];   // x split (A-side; also B for scores)
__device__ __half g_xl [(size_t)NB * NS * ND];
__device__ __half g_xth[(size_t)NB * ND * NS];   // x^T per batch (B-side, hi only)
__device__ __half g_ah [(size_t)NB * NS * NS];   // attn probs split (A-side)
__device__ __half g_al [(size_t)NB * NS * NS];
__device__ __half g_hh [(size_t)NB * NS * NF];   // ffn hidden split (A-side)
__device__ __half g_hl [(size_t)NB * NS * NF];
__device__ __half g_w1h[(size_t)NL * NF * ND];   // w1^T hi (B-side)
__device__ __half g_w2h[(size_t)NL * ND * NF];   // w2^T hi
__device__ __half g_wvh[(size_t)NV * ND];        // headW^T hi

// ---------------------------------------------------------------------------
// Helpers
// ---------------------------------------------------------------------------
__device__ __forceinline__ uint32_t smem_u32(const void* p) {
    return (uint32_t)__cvta_generic_to_shared(p);
}
__device__ __forceinline__ void split_f16(float v, __half& h, __half& l) {
    h = __float2half_rn(v);
    l = __float2half_rn(v - __half2float(h));
}

#define CP16(smem, gptr) \
    asm volatile("cp.async.cg.shared.global [%0], [%1], 16;" :: "r"(smem), "l"(gptr))
#define CP_COMMIT() asm volatile("cp.async.commit_group;" ::: "memory")
#define CP_WAIT0() asm volatile("cp.async.wait_group 0;" ::: "memory")
#define CP_WAIT1() asm volatile("cp.async.wait_group 1;" ::: "memory")
#define CP_WAIT2() asm volatile("cp.async.wait_group 2;" ::: "memory")

#define LDSM_X4(r0, r1, r2, r3, addr) \
    asm volatile("ldmatrix.sync.aligned.m8n8.x4.shared.b16 {%0,%1,%2,%3}, [%4];" \
                 : "=r"(r0), "=r"(r1), "=r"(r2), "=r"(r3) : "r"(addr))

#define MMA16816(c, a, b) \
    asm("mma.sync.aligned.m16n8k16.row.col.f32.f16.f16.f32 " \
        "{%0,%1,%2,%3}, {%4,%5,%6,%7}, {%8,%9}, {%0,%1,%2,%3};" \
        : "+f"((c)[0]), "+f"((c)[1]), "+f"((c)[2]), "+f"((c)[3]) \
        : "r"((a)[0]), "r"((a)[1]), "r"((a)[2]), "r"((a)[3]), "r"((b)[0]), "r"((b)[1]))

// ---------------------------------------------------------------------------
// HMMA GEMM (fp16 split-A): C = alpha*(Ah@Bh^T + Al@Bh^T [+ Ah@Bl^T]) (+bias)(+relu)
// A as Ah/Al [M,K] row-major; B as Bh (and Bl when THREE) [N,K] row-major.
// Tile BM=64, BN=128, BK=32; 256 threads, warps 2x4 (warp tile 32x32).
// 3-stage cp.async pipeline, 2 CTAs/SM, full-chunk fragment prefetch (2-pass).
// SPLIT: write half hi/lo. PACKED: causal lower-triangle packed grid.
// CKLIM: K -> brow+64 (A zero beyond diagonal).
// ---------------------------------------------------------------------------
static constexpr int A_TILE = 64 * 80;     // 5120 B per A operand tile
static constexpr int B_TILE = 128 * 80;    // 10240 B per B operand tile
static constexpr int AH_O = 0, AL_O = 5120, BH_O = 10240, BL_O = 20480;
template<bool THREE> struct Cfg {
    static constexpr int STAGE_B = THREE ? 30720 : 20480;
    static constexpr int SMEM    = 3 * STAGE_B;
};

template<bool RELU, bool SPLIT, bool PACKED, bool CKLIM, bool THREE>
__global__ __launch_bounds__(256, 2)
void hmma_gemm(const __half* __restrict__ Ah, const __half* __restrict__ Al,
               const __half* __restrict__ Bh, const __half* __restrict__ Bl,
               float* __restrict__ C, __half* __restrict__ Ch, __half* __restrict__ Cl,
               int M, int N, int K,
               long sA, long sB, long sC,
               float alpha, const float* __restrict__ bias)
{
    constexpr int STAGE_B = Cfg<THREE>::STAGE_B;

    int brow, bcol;
    if (PACKED) {
        // decode packed lower-triangle tile index: rows of 64, cols of 128
        int t = blockIdx.x, i = 0;
        while (true) { int w = (i >> 1) + 1; if (t < w) break; t -= w; i++; }
        brow = i * 64; bcol = t * 128;
    } else {
        brow = blockIdx.y * 64;
        bcol = blockIdx.x * 128;
    }

    Ah += (long)blockIdx.z * sA;  Al += (long)blockIdx.z * sA;
    Bh += (long)blockIdx.z * sB;
    if (THREE) Bl += (long)blockIdx.z * sB;
    if (C)  C  += (long)blockIdx.z * sC;
    if (Ch) { Ch += (long)blockIdx.z * sC; Cl += (long)blockIdx.z * sC; }

    const int tid  = threadIdx.x;
    const int wid  = tid >> 5;
    const int lane = tid & 31;
    const int wm   = wid & 1;          // warp row (0..1) -> 32 rows
    const int wn   = wid >> 1;         // warp col (0..3) -> 32 cols

    const int K_eff = CKLIM ? (brow + 64 < K ? brow + 64 : K) : K;
    const int nk = K_eff >> 5;

    extern __shared__ __align__(16) char dsm[];
    const uint32_t sbase = smem_u32(dsm);
    __shared__ float s_bias[128];
    if (tid < 128) s_bias[tid] = bias ? bias[bcol + tid] : 0.0f;

    float acc[2][4][4] = {};   // [mi][ni][frag]

    const int a_row = (lane & 15);
    const int a_ko  = (lane >> 4) << 3;
    const int b_row = ((lane >> 4) << 3) + (lane & 7);
    const int b_ko  = ((lane >> 3) & 1) << 3;

    // loader: 1024 (2-pass) or 1536 (THREE) 16B chunks per stage
    auto load_stage = [&](int stage, int kk) {
        const uint32_t sb = sbase + stage * STAGE_B;
        #pragma unroll
        for (int i = 0; i < (THREE ? 6 : 4); i++) {
            int chunk = tid + i * 256;
            const __half* g;
            uint32_t so;
            if (chunk < 512) {          // A tiles: Ah [0,256), Al [256,512)
                int op = chunk >> 8, w = chunk & 255;
                int r = w >> 2, c = w & 3;
                g  = (op ? Al : Ah) + (long)(brow + r) * K + kk + c * 8;
                so = sb + (op ? AL_O : AH_O) + r * 80 + c * 16;
            } else {                    // B tiles: Bh [512,1024), Bl [1024,1536)
                int j = chunk - 512;
                int op = j >> 9, w = j & 511;
                int r = w >> 2, c = w & 3;
                g  = (op ? Bl : Bh) + (long)(bcol + r) * K + kk + c * 8;
                so = sb + (op ? BL_O : BH_O) + r * 80 + c * 16;
            }
            CP16(so, g);
        }
    };

    // prologue: 3 stages in flight
    load_stage(0, 0); CP_COMMIT();
    if (nk > 1) { load_stage(1, 32); CP_COMMIT(); }
    if (nk > 2) { load_stage(2, 64); CP_COMMIT(); }

    for (int kc = 0; kc < nk; kc++) {
        const int rem = nk - 1 - kc;
        if (rem >= 2)      CP_WAIT2();
        else if (rem == 1) CP_WAIT1();
        else               CP_WAIT0();
        __syncthreads();

        const uint32_t st = sbase + (kc % 3) * STAGE_B;
        const uint32_t ahb = st + AH_O;
        const uint32_t alb = st + AL_O;
        const uint32_t bhb = st + BH_O;
        const uint32_t blb = st + BL_O;

        if (THREE) {
            // per-ks structure (frag regs too tight for full-chunk prefetch)
            #pragma unroll
            for (int ks = 0; ks < 2; ks++) {
                const int ak = (ks * 16 + a_ko) * 2;
                const int bk = (ks * 16 + b_ko) * 2;
                uint32_t af[2][4], alf[2][4], bf[4][2], lf[4][2];
                #pragma unroll
                for (int mi = 0; mi < 2; mi++) {
                    LDSM_X4(af[mi][0], af[mi][1], af[mi][2], af[mi][3],
                            ahb + (wm * 32 + mi * 16 + a_row) * 80 + ak);
                    LDSM_X4(alf[mi][0], alf[mi][1], alf[mi][2], alf[mi][3],
                            alb + (wm * 32 + mi * 16 + a_row) * 80 + ak);
                }
                #pragma unroll
                for (int p = 0; p < 2; p++) {
                    LDSM_X4(bf[2*p][0], bf[2*p][1], bf[2*p+1][0], bf[2*p+1][1],
                            bhb + (wn * 32 + p * 16 + b_row) * 80 + bk);
                    LDSM_X4(lf[2*p][0], lf[2*p][1], lf[2*p+1][0], lf[2*p+1][1],
                            blb + (wn * 32 + p * 16 + b_row) * 80 + bk);
                }
                #pragma unroll
                for (int mi = 0; mi < 2; mi++)
                    #pragma unroll
                    for (int ni = 0; ni < 4; ni++) {
                        MMA16816(acc[mi][ni], af[mi],  bf[ni]);   // Ah*Bh
                        MMA16816(acc[mi][ni], af[mi],  lf[ni]);   // Ah*Bl
                        MMA16816(acc[mi][ni], alf[mi], bf[ni]);   // Al*Bh
                    }
            }
        } else {
            // full-chunk fragment prefetch: all LDSM for both ks, then all MMA
            uint32_t af[2][2][4], alf[2][2][4], bf[2][4][2];
            #pragma unroll
            for (int ks = 0; ks < 2; ks++) {
                const int ak = (ks * 16 + a_ko) * 2;
                const int bk = (ks * 16 + b_ko) * 2;
                #pragma unroll
                for (int mi = 0; mi < 2; mi++) {
                    LDSM_X4(af[ks][mi][0], af[ks][mi][1], af[ks][mi][2], af[ks][mi][3],
                            ahb + (wm * 32 + mi * 16 + a_row) * 80 + ak);
                    LDSM_X4(alf[ks][mi][0], alf[ks][mi][1], alf[ks][mi][2], alf[ks][mi][3],
                            alb + (wm * 32 + mi * 16 + a_row) * 80 + ak);
                }
                #pragma unroll
                for (int p = 0; p < 2; p++)
                    LDSM_X4(bf[ks][2*p][0], bf[ks][2*p][1], bf[ks][2*p+1][0], bf[ks][2*p+1][1],
                            bhb + (wn * 32 + p * 16 + b_row) * 80 + bk);
            }
            #pragma unroll
            for (int ks = 0; ks < 2; ks++)
                #pragma unroll
                for (int mi = 0; mi < 2; mi++)
                    #pragma unroll
                    for (int ni = 0; ni < 4; ni++) {
                        MMA16816(acc[mi][ni], af[ks][mi],  bf[ks][ni]);   // Ah*Bh
                        MMA16816(acc[mi][ni], alf[ks][mi], bf[ks][ni]);   // Al*Bh
                    }
        }
        __syncthreads();

        if (kc + 3 < nk) { load_stage((kc + 3) % 3, (kc + 3) * 32); CP_COMMIT(); }
    }

    // epilogue
    const int g4 = lane >> 2, t4 = lane & 3;
    #pragma unroll
    for (int mi = 0; mi < 2; mi++) {
        const int r0 = brow + wm * 32 + mi * 16 + g4;
        #pragma unroll
        for (int ni = 0; ni < 4; ni++) {
            const int cl = wn * 32 + ni * 8 + t4 * 2;
            const int c0 = bcol + cl;
            float v0 = acc[mi][ni][0] * alpha + s_bias[cl];
            float v1 = acc[mi][ni][1] * alpha + s_bias[cl + 1];
            float v2 = acc[mi][ni][2] * alpha + s_bias[cl];
            float v3 = acc[mi][ni][3] * alpha + s_bias[cl + 1];
            if (RELU) {
                v0 = fmaxf(v0, 0.0f); v1 = fmaxf(v1, 0.0f);
                v2 = fmaxf(v2, 0.0f); v3 = fmaxf(v3, 0.0f);
            }
            if (SPLIT) {
                __half h0, l0, h1, l1;
                __half2 hp, lp;
                long b0 = (long)r0 * N + c0;
                split_f16(v0, h0, l0); split_f16(v1, h1, l1);
                hp = __halves2half2(h0, h1); lp = __halves2half2(l0, l1);
                *(__half2*)(Ch + b0) = hp;
                *(__half2*)(Cl + b0) = lp;
                long b1 = (long)(r0 + 8) * N + c0;
                split_f16(v2, h0, l0); split_f16(v3, h1, l1);
                hp = __halves2half2(h0, h1); lp = __halves2half2(l0, l1);
                *(__half2*)(Ch + b1) = hp;
                *(__half2*)(Cl + b1) = lp;
            } else {
                float2 p0 = { v0, v1 }, p1 = { v2, v3 };
                *(float2*)(C + (long)r0 * N + c0)       = p0;
                *(float2*)(C + (long)(r0 + 8) * N + c0) = p1;
            }
        }
    }
}

// ---------------------------------------------------------------------------
// Transpose + fp16 split: oh[c][r] (+ol) = split(in[r][c]); ol may be null.
// ---------------------------------------------------------------------------
__global__ void transpose_split_kernel(const float* __restrict__ in,
                                       __half* __restrict__ oh,
                                       __half* __restrict__ ol,
                                       int R, int C, long sIn, long sOut)
{
    __shared__ float t[32][33];
    in += (long)blockIdx.z * sIn;
    oh += (long)blockIdx.z * sOut;
    if (ol) ol += (long)blockIdx.z * sOut;
    int r0 = blockIdx.y * 32, c0 = blockIdx.x * 32;
    int tx = threadIdx.x, ty = threadIdx.y;
    #pragma unroll
    for (int k = 0; k < 32; k += 8)
        t[ty + k][tx] = in[(long)(r0 + ty + k) * C + c0 + tx];
    __syncthreads();
    #pragma unroll
    for (int k = 0; k < 32; k += 8) {
        float v = t[tx][ty + k];
        long o = (long)(c0 + ty + k) * R + r0 + tx;
        __half h, l; split_f16(v, h, l);
        oh[o] = h;
        if (ol) ol[o] = l;
    }
}

// ---------------------------------------------------------------------------
// Embedding (+ split)
// ---------------------------------------------------------------------------
__global__ void embed_kernel(const int* __restrict__ tokens,
                             const float* __restrict__ emb,
                             const float* __restrict__ pe,
                             float* __restrict__ x,
                             __half* __restrict__ xh, __half* __restrict__ xl)
{
    int row = blockIdx.x;
    int s = row & (NS - 1);
    int tok = tokens[row];
    const float scale = 32.0f;
    const float* e = emb + (long)tok * ND;
    const float* p = pe + (long)s * ND;
    long base = (long)row * ND;
    for (int d = threadIdx.x; d < ND; d += blockDim.x) {
        float v = e[d] * scale + p[d];
        x[base + d] = v;
        __half h, l; split_f16(v, h, l);
        xh[base + d] = h; xl[base + d] = l;
    }
}

// ---------------------------------------------------------------------------
// Causal softmax in place (+ split attn probs)
// ---------------------------------------------------------------------------
__global__ __launch_bounds__(256)
void softmax_kernel(float* __restrict__ attn,
                    __half* __restrict__ ah, __half* __restrict__ al)
{
    int row = blockIdx.x;            // b*S + s
    int s = row & (NS - 1);
    long base = (long)row * NS;
    float* p = attn + base;
    int tid = threadIdx.x;
    __shared__ float red[256];

    float vals[4];
    float mx = -1e30f;
    #pragma unroll
    for (int it = 0; it < 4; it++) {
        int j = tid + it * 256;
        float v = (j <= s) ? p[j] : -1e30f;
        vals[it] = v;
        mx = fmaxf(mx, v);
    }
    red[tid] = mx; __syncthreads();
    for (int o = 128; o > 0; o >>= 1) {
        if (tid < o) red[tid] = fmaxf(red[tid], red[tid + o]);
        __syncthreads();
    }
    mx = red[0]; __syncthreads();

    float sum = 0.0f;
    #pragma unroll
    for (int it = 0; it < 4; it++) {
        int j = tid + it * 256;
        float e = (j <= s) ? __expf(vals[it] - mx) : 0.0f;
        vals[it] = e;
        sum += e;
    }
    red[tid] = sum; __syncthreads();
    for (int o = 128; o > 0; o >>= 1) {
        if (tid < o) red[tid] += red[tid + o];
        __syncthreads();
    }
    float inv = 1.0f / red[0];
    #pragma unroll
    for (int it = 0; it < 4; it++) {
        int j = tid + it * 256;
        float v = vals[it] * inv;
        p[j] = v;
        __half h, l; split_f16(v, h, l);
        ah[base + j] = h; al[base + j] = l;
    }
}

// ---------------------------------------------------------------------------
// LayerNorm of (x + res) (+ split). res may be null.
// ---------------------------------------------------------------------------
__global__ __launch_bounds__(256)
void ln_kernel(const float* __restrict__ x, const float* __restrict__ res,
               const float* __restrict__ g, const float* __restrict__ b,
               float* __restrict__ out,
               __half* __restrict__ oh, __half* __restrict__ ol)
{
    int row = blockIdx.x;
    long base = (long)row * ND;
    const float* xr = x + base;
    const float* rr = res ? res + base : nullptr;
    int tid = threadIdx.x;
    __shared__ float red[256];

    float v[4];
    float lsum = 0.0f;
    #pragma unroll
    for (int it = 0; it < 4; it++) {
        int j = tid + it * 256;
        float t = xr[j] + (rr ? rr[j] : 0.0f);
        v[it] = t;
        lsum += t;
    }
    red[tid] = lsum; __syncthreads();
    for (int o2 = 128; o2 > 0; o2 >>= 1) {
        if (tid < o2) red[tid] += red[tid + o2];
        __syncthreads();
    }
    float mu = red[0] * (1.0f / ND); __syncthreads();

    float lvar = 0.0f;
    #pragma unroll
    for (int it = 0; it < 4; it++) {
        float d = v[it] - mu;
        lvar += d * d;
    }
    red[tid] = lvar; __syncthreads();
    for (int o2 = 128; o2 > 0; o2 >>= 1) {
        if (tid < o2) red[tid] += red[tid + o2];
        __syncthreads();
    }
    float rstd = rsqrtf(red[0] * (1.0f / ND) + 1e-5f);

    #pragma unroll
    for (int it = 0; it < 4; it++) {
        int j = tid + it * 256;
        float o = (v[it] - mu) * rstd * g[j] + b[j];
        out[base + j] = o;
        __half h, l; split_f16(o, h, l);
        oh[base + j] = h; ol[base + j] = l;
    }
}

// ---------------------------------------------------------------------------
// Launch
// ---------------------------------------------------------------------------
extern "C" void kernel_launch(void* const* d_in, const int* in_sizes, int n_in,
                              void* d_out, int out_size)
{
    const int*   tokens = (const int*)  d_in[0];
    const float* emb    = (const float*)d_in[2];
    const float* pe     = (const float*)d_in[3];
    const float* ln1_g  = (const float*)d_in[4];
    const float* ln1_b  = (const float*)d_in[5];
    const float* w1     = (const float*)d_in[6];
    const float* b1     = (const float*)d_in[7];
    const float* w2     = (const float*)d_in[8];
    const float* b2     = (const float*)d_in[9];
    const float* ln2_g  = (const float*)d_in[10];
    const float* ln2_b  = (const float*)d_in[11];
    const float* lnf_g  = (const float*)d_in[12];
    const float* lnf_b  = (const float*)d_in[13];
    const float* headW  = (const float*)d_in[14];
    const float* headb  = (const float*)d_in[15];

    float* out      = (float*)d_out;
    float* logits   = out;                               // [B,S,V]
    float* attn_all = out + (long)NB * NS * NV;          // [L,B,S,S]

    float *x, *tmp;
    cudaGetSymbolAddress((void**)&x,   g_x);
    cudaGetSymbolAddress((void**)&tmp, g_tmp);
    __half *xh, *xl, *xth, *ah, *al, *hh, *hl, *w1h, *w2h, *wvh;
    cudaGetSymbolAddress((void**)&xh,  g_xh);  cudaGetSymbolAddress((void**)&xl,  g_xl);
    cudaGetSymbolAddress((void**)&xth, g_xth);
    cudaGetSymbolAddress((void**)&ah,  g_ah);  cudaGetSymbolAddress((void**)&al,  g_al);
    cudaGetSymbolAddress((void**)&hh,  g_hh);  cudaGetSymbolAddress((void**)&hl,  g_hl);
    cudaGetSymbolAddress((void**)&w1h, g_w1h);
    cudaGetSymbolAddress((void**)&w2h, g_w2h);
    cudaGetSymbolAddress((void**)&wvh, g_wvh);

    const int SM2 = Cfg<false>::SMEM;   // 61440
    const int SM3 = Cfg<true>::SMEM;    // 92160
    cudaFuncSetAttribute(hmma_gemm<false, false, true,  false, true>,
                         cudaFuncAttributeMaxDynamicSharedMemorySize, SM3);
    cudaFuncSetAttribute(hmma_gemm<false, false, false, true,  false>,
                         cudaFuncAttributeMaxDynamicSharedMemorySize, SM2);
    cudaFuncSetAttribute(hmma_gemm<true,  true,  false, false, false>,
                         cudaFuncAttributeMaxDynamicSharedMemorySize, SM2);
    cudaFuncSetAttribute(hmma_gemm<false, false, false, false, false>,
                         cudaFuncAttributeMaxDynamicSharedMemorySize, SM2);

    const int ROWS = NB * NS;           // 4096
    const dim3 tb(32, 8);

    // Launch order: scores GEMM is the 4th launch (ncu profiles it).
    embed_kernel<<<ROWS, 256>>>(tokens, emb, pe, x, xh, xl);
    transpose_split_kernel<<<dim3(NV / 32, ND / 32, 1), tb>>>(
        headW, wvh, nullptr, ND, NV, 0, 0);

    for (int l = 0; l < NL; l++) {
        float* attnL = attn_all + (long)l * NB * NS * NS;

        // x^T per batch (B-operand of attn@x, hi only)
        transpose_split_kernel<<<dim3(ND / 32, NS / 32, NB), tb>>>(
            x, xth, nullptr, NS, ND, (long)NS * ND, (long)ND * NS);

        // scores = x @ x^T / 32 (packed causal grid: 72 tiles; 3-pass)
        hmma_gemm<false, false, true, false, true><<<dim3(72, 1, NB), 256, SM3>>>(
            xh, xl, xh, xl, attnL, nullptr, nullptr,
            NS, NS, ND, (long)NS * ND, (long)NS * ND, (long)NS * NS,
            1.0f / 32.0f, nullptr);

        softmax_kernel<<<ROWS, 256>>>(attnL, ah, al);

        // attn_out = attn @ x (K truncated at diagonal; 2-pass)
        hmma_gemm<false, false, false, true, false><<<dim3(8, 16, NB), 256, SM2>>>(
            ah, al, xth, nullptr, tmp, nullptr, nullptr,
            NS, ND, NS, (long)NS * NS, (long)ND * NS, (long)NS * ND,
            1.0f, nullptr);

        ln_kernel<<<ROWS, 256>>>(x, tmp, ln1_g + l * ND, ln1_b + l * ND, x, xh, xl);

        if (l == 0) {   // weight transposes (hi only), once, before first FFN
            transpose_split_kernel<<<dim3(NF / 32, ND / 32, NL), tb>>>(
                w1, w1h, nullptr, ND, NF, (long)ND * NF, (long)NF * ND);
            transpose_split_kernel<<<dim3(ND / 32, NF / 32, NL), tb>>>(
                w2, w2h, nullptr, NF, ND, (long)NF * ND, (long)ND * NF);
        }

        // h = relu(x @ w1 + b1)  -> split fp16 (2-pass)
        hmma_gemm<true, true, false, false, false><<<dim3(NF / 128, ROWS / 64, 1), 256, SM2>>>(
            xh, xl, w1h + (long)l * NF * ND, nullptr,
            nullptr, hh, hl,
            ROWS, NF, ND, 0, 0, 0, 1.0f, b1 + (long)l * NF);

        // ffn_out = h @ w2 + b2 (2-pass)
        hmma_gemm<false, false, false, false, false><<<dim3(ND / 128, ROWS / 64, 1), 256, SM2>>>(
            hh, hl, w2h + (long)l * ND * NF, nullptr,
            tmp, nullptr, nullptr,
            ROWS, ND, NF, 0, 0, 0, 1.0f, b2 + (long)l * ND);

        ln_kernel<<<ROWS, 256>>>(x, tmp, ln2_g + l * ND, ln2_b + l * ND, x, xh, xl);
    }

    ln_kernel<<<ROWS, 256>>>(x, nullptr, lnf_g, lnf_b, x, xh, xl);

    // logits = x @ headW + headb (2-pass)
    hmma_gemm<false, false, false, false, false><<<dim3(NV / 128, ROWS / 64, 1), 256, SM2>>>(
        xh, xl, wvh, nullptr, logits, nullptr, nullptr,
        ROWS, NV, ND, 0, 0, 0, 1.0f, headb);
}